// round 12
// baseline (speedup 1.0000x reference)
#include <cuda_runtime.h>
#include <cuda_fp16.h>
#include <cstdint>

// ----------------------------------------------------------------------------
// Problem constants
// ----------------------------------------------------------------------------
#define DIM 128            // input dim d
#define BATCH 4096
#define HID 512            // 2*OUTPUT_DIM
#define OUTD 256
#define KTOT (DIM * DIM)   // 16384
#define KC 128             // K chunk = one full i-block (j = 0..127)
#define NCHUNK (KTOT / KC) // 128
#define NSTAGE 3

// GEMM1: full job = 128(M) x 64(N); quarter job = 32(M) x 64(N)
#define NFULL 148
#define NQUART 432         // (256-148) tiles x 4
#define G1_GRID (NFULL + NQUART)   // 580

#define XS_STRIDE 136      // fp16 x-tile row stride (halfs)  -> conflict-free ldmatrix
#define BS_STRIDE 136      // fp16 B-stage row stride (halfs) -> conflict-free ldmatrix
#define XS_HALFS (128 * XS_STRIDE)              // 17408 halfs = 34816 B
#define BS_STAGE_HALFS (64 * BS_STRIDE)         // 8704 halfs  = 17408 B
#define BS_STAGE_BYTES (BS_STAGE_HALFS * 2)
#define G1_SMEM_BYTES ((XS_HALFS + NSTAGE * BS_STAGE_HALFS) * 2)   // 87040 B

// Layer2: stage all of K=512 in smem
#define L2_STRIDE 520      // halfs; 1040B rows -> bank residue 4, conflict-free ldmatrix
#define L2_A_BYTES (128 * L2_STRIDE * 2)        // 133120
#define L2_B_BYTES (64 * L2_STRIDE * 2)         // 66560
#define L2_SMEM_BYTES (L2_A_BYTES + L2_B_BYTES) // 199680

// ----------------------------------------------------------------------------
// Device scratch (static allocation: allowed)
// ----------------------------------------------------------------------------
// W1sym^T fp16, [n][k], k=(i,j): j>i: W1[ij]+W1[ji]; j==i: W1[ii]; j<i: 0
__device__ __half g_w1t[HID * KTOT];     // 16.8MB
__device__ __half g_h[BATCH * HID];      // hidden activations, fp16 (4MB)
__device__ __half g_w2t[OUTD * HID];     // W2^T fp16 [n][k] (256KB)

// ----------------------------------------------------------------------------
// Helpers
// ----------------------------------------------------------------------------
__device__ __forceinline__ uint32_t smem_u32(const void* p) {
    uint32_t a;
    asm("{ .reg .u64 t; cvta.to.shared.u64 t, %1; cvt.u32.u64 %0, t; }" : "=r"(a) : "l"(p));
    return a;
}
__device__ __forceinline__ void cp_async16(uint32_t smem_addr, const void* gptr) {
    asm volatile("cp.async.cg.shared.global [%0], [%1], 16;" :: "r"(smem_addr), "l"(gptr) : "memory");
}
#define CP_COMMIT() asm volatile("cp.async.commit_group;" ::: "memory")
#define CP_WAIT(n)  asm volatile("cp.async.wait_group %0;" :: "n"(n) : "memory")

#define LDSM4(r, addr) \
    asm volatile("ldmatrix.sync.aligned.m8n8.x4.shared.b16 {%0,%1,%2,%3}, [%4];" \
        : "=r"((r)[0]), "=r"((r)[1]), "=r"((r)[2]), "=r"((r)[3]) : "r"(addr))

#define MMA_F16(d, a, bb0, bb1) \
    asm volatile("mma.sync.aligned.m16n8k16.row.col.f32.f16.f16.f32 " \
        "{%0,%1,%2,%3}, {%4,%5,%6,%7}, {%8,%9}, {%0,%1,%2,%3};" \
        : "+f"((d)[0]), "+f"((d)[1]), "+f"((d)[2]), "+f"((d)[3]) \
        : "r"((a)[0]), "r"((a)[1]), "r"((a)[2]), "r"((a)[3]), "r"(bb0), "r"(bb1))

// ----------------------------------------------------------------------------
// Kernel 1: symmetrize + transpose + fp16-convert W1.
// ----------------------------------------------------------------------------
__global__ __launch_bounds__(256) void k_w1sym(const float* __restrict__ W1) {
    __shared__ float ssum[128][33];
    const int i  = blockIdx.x;           // 0..127
    const int nb = blockIdx.y * 32;
    const int tx = threadIdx.x, ty = threadIdx.y;
    #pragma unroll
    for (int r = 0; r < 16; r++) {
        int j = ty + r * 8;
        float v = 0.0f;
        if (j > i) {
            v = W1[(size_t)(i * DIM + j) * HID + nb + tx]
              + W1[(size_t)(j * DIM + i) * HID + nb + tx];
        } else if (j == i) {
            v = W1[(size_t)(i * DIM + i) * HID + nb + tx];
        }
        ssum[j][tx] = v;
    }
    __syncthreads();
    #pragma unroll
    for (int r = 0; r < 4; r++) {
        int n = ty + r * 8;
        int j4 = tx * 4;
        __half2 h0 = __floats2half2_rn(ssum[j4 + 0][n], ssum[j4 + 1][n]);
        __half2 h1 = __floats2half2_rn(ssum[j4 + 2][n], ssum[j4 + 3][n]);
        uint2 pk = make_uint2(*(uint32_t*)&h0, *(uint32_t*)&h1);
        *(uint2*)(g_w1t + (size_t)(nb + n) * KTOT + i * DIM + j4) = pk;
    }
}

// ----------------------------------------------------------------------------
// Kernel 1b: transpose + fp16-convert W2 [512][256] -> g_w2t [256][512]
// ----------------------------------------------------------------------------
__global__ __launch_bounds__(256) void k_w2t(const float* __restrict__ W2) {
    __shared__ float t[32][66];
    const int kb = blockIdx.x * 64;
    const int nb = blockIdx.y * 32;
    const int tx = threadIdx.x, ty = threadIdx.y;
    #pragma unroll
    for (int r = 0; r < 8; r++) {
        int k = ty + r * 8;
        t[tx][k] = W2[(size_t)(kb + k) * OUTD + nb + tx];
    }
    __syncthreads();
    #pragma unroll
    for (int r = 0; r < 4; r++) {
        int n = ty + r * 8;
        __half2 h = __floats2half2_rn(t[n][tx * 2], t[n][tx * 2 + 1]);
        *(__half2*)(g_w2t + (size_t)(nb + n) * HID + kb + tx * 2) = h;
    }
}

// ----------------------------------------------------------------------------
// Kernel 2: H = relu( (d * x (x) x) @ W1 + b1 )  — symmetric triangle.
//   Job mix for wave balance: bids 0..147 = full tiles (M128xN64, one per SM
//   in wave 1); bids 148..579 = quarter tiles (M32xN64) that stream into the
//   second CTA slot.
// ----------------------------------------------------------------------------
#define G1_PREFETCH_B(c_) do {                                                   \
    const int c__ = (c_);                                                        \
    const int smin__ = (c__ >> 4) * 2;                                           \
    const uint32_t buf__ = (uint32_t)(c__ % NSTAGE) * BS_STAGE_BYTES;            \
    const int kbase__ = c__ * KC;                                                \
    _Pragma("unroll")                                                            \
    for (int r__ = 0; r__ < 4; r__++) {                                          \
        int id__ = tid + r__ * 256;                                              \
        int row__ = id__ >> 4;                                                   \
        int seg__ = id__ & 15;                                                   \
        if (seg__ >= smin__)                                                     \
            cp_async16(bs_b + buf__ + (uint32_t)(row__ * (BS_STRIDE * 2) + seg__ * 16), \
                       w1g + (size_t)(n0 + row__) * KTOT + kbase__ + seg__ * 8); \
    }                                                                            \
} while (0)

__global__ __launch_bounds__(256, 2) void k_gemm1(const float* __restrict__ x,
                                                  const float* __restrict__ bias1) {
    extern __shared__ char smem_raw[];
    __half* xsh = (__half*)smem_raw;                 // [<=128][XS_STRIDE]
    __half* bsm = xsh + XS_HALFS;                    // NSTAGE x [64][BS_STRIDE]
    const uint32_t xs_b = smem_u32(xsh);
    const uint32_t bs_b = smem_u32(bsm);

    const int tid  = threadIdx.x;
    const int lane = tid & 31;
    const int wid  = tid >> 5;
    const int gid  = lane >> 2;          // 0..7
    const int tg   = lane & 3;           // 0..3
    const int l7   = lane & 7;

    // ---- job decode ----
    const int job = blockIdx.x;
    int tile, msub, isFull;
    if (job < NFULL) { isFull = 1; tile = job; msub = 0; }
    else { int q = job - NFULL; isFull = 0; tile = NFULL + (q >> 2); msub = q & 3; }
    const int m0 = (tile & 31) * 128 + msub * 32;
    const int n0 = (tile >> 5) * 64;
    const int MR = isFull ? 128 : 32;

    const __half* w1g = g_w1t;

    // ---- prefetch B stages 0 and 1 ----
    G1_PREFETCH_B(0);
    CP_COMMIT();
    G1_PREFETCH_B(1);
    CP_COMMIT();

    // ---- stage x tile (MR rows) as fp16 ----
    for (int r = 0; r < (MR >> 3); r++) {
        int id = tid + r * 256;
        int m = id >> 5, c4 = id & 31;
        float4 v = *(const float4*)(x + (size_t)(m0 + m) * DIM + c4 * 4);
        __half2 h0 = __floats2half2_rn(v.x, v.y);
        __half2 h1 = __floats2half2_rn(v.z, v.w);
        uint2 pk = make_uint2(*(uint32_t*)&h0, *(uint32_t*)&h1);
        *(uint2*)(xsh + m * XS_STRIDE + c4 * 4) = pk;
    }
    __syncthreads();

    if (isFull) {
        // ==================== FULL PATH: 128 x 64, warp tile 32x32 ====================
        const int wm = wid & 3, wn = wid >> 2;
        int rowt[4];
        rowt[0] = m0 + wm * 32 + gid;
        rowt[1] = rowt[0] + 8;
        rowt[2] = rowt[0] + 16;
        rowt[3] = rowt[0] + 24;

        const uint32_t aAddr = xs_b +
            (uint32_t)(((wm * 32 + l7 + ((lane >> 3) & 1) * 8) * XS_STRIDE + ((lane >> 4) & 1) * 8) * 2);
        const uint32_t bAddr = bs_b +
            (uint32_t)(((wn * 32 + l7 + ((lane >> 4) & 1) * 8) * BS_STRIDE + ((lane >> 3) & 1) * 8) * 2);

        float acc[2][4][4];
        #pragma unroll
        for (int mt = 0; mt < 2; mt++)
            #pragma unroll
            for (int nt = 0; nt < 4; nt++)
                #pragma unroll
                for (int q = 0; q < 4; q++) acc[mt][nt][q] = 0.0f;

        #pragma unroll 1
        for (int it = 0; it < NCHUNK; it++) {
            float xi[4];
            #pragma unroll
            for (int t = 0; t < 4; t++)
                xi[t] = 128.0f * __ldg(x + (size_t)rowt[t] * DIM + it);

            CP_WAIT(1);
            __syncthreads();
            if (it + 2 < NCHUNK) G1_PREFETCH_B(it + 2);
            CP_COMMIT();

            const uint32_t bStage = bAddr + (uint32_t)(it % NSTAGE) * BS_STAGE_BYTES;
            float p[2][4][4];
            #pragma unroll
            for (int mt = 0; mt < 2; mt++)
                #pragma unroll
                for (int nt = 0; nt < 4; nt++)
                    #pragma unroll
                    for (int q = 0; q < 4; q++) p[mt][nt][q] = 0.0f;

            const int s0 = it >> 4;
            for (int s = s0; s < 8; s++) {
                uint32_t a0[4], a1[4], bA[4], bB[4];
                LDSM4(a0, aAddr + (uint32_t)(s * 32));
                LDSM4(a1, aAddr + (uint32_t)(16 * XS_STRIDE * 2 + s * 32));
                LDSM4(bA, bStage + (uint32_t)(s * 32));
                LDSM4(bB, bStage + (uint32_t)(16 * BS_STRIDE * 2 + s * 32));
                MMA_F16(p[0][0], a0, bA[0], bA[1]);
                MMA_F16(p[1][0], a1, bA[0], bA[1]);
                MMA_F16(p[0][1], a0, bA[2], bA[3]);
                MMA_F16(p[1][1], a1, bA[2], bA[3]);
                MMA_F16(p[0][2], a0, bB[0], bB[1]);
                MMA_F16(p[1][2], a1, bB[0], bB[1]);
                MMA_F16(p[0][3], a0, bB[2], bB[3]);
                MMA_F16(p[1][3], a1, bB[2], bB[3]);
            }
            #pragma unroll
            for (int mt = 0; mt < 2; mt++)
                #pragma unroll
                for (int nt = 0; nt < 4; nt++) {
                    acc[mt][nt][0] = fmaf(xi[mt * 2],     p[mt][nt][0], acc[mt][nt][0]);
                    acc[mt][nt][1] = fmaf(xi[mt * 2],     p[mt][nt][1], acc[mt][nt][1]);
                    acc[mt][nt][2] = fmaf(xi[mt * 2 + 1], p[mt][nt][2], acc[mt][nt][2]);
                    acc[mt][nt][3] = fmaf(xi[mt * 2 + 1], p[mt][nt][3], acc[mt][nt][3]);
                }
        }

        // epilogue: +b1, relu, fp16 store
        #pragma unroll
        for (int mt = 0; mt < 2; mt++) {
            #pragma unroll
            for (int nt = 0; nt < 4; nt++) {
                int col = n0 + wn * 32 + nt * 8 + tg * 2;
                float bb0 = bias1[col], bb1 = bias1[col + 1];
                int rowA = m0 + wm * 32 + mt * 16 + gid;
                *(__half2*)(g_h + (size_t)rowA * HID + col) =
                    __floats2half2_rn(fmaxf(acc[mt][nt][0] + bb0, 0.0f),
                                      fmaxf(acc[mt][nt][1] + bb1, 0.0f));
                *(__half2*)(g_h + (size_t)(rowA + 8) * HID + col) =
                    __floats2half2_rn(fmaxf(acc[mt][nt][2] + bb0, 0.0f),
                                      fmaxf(acc[mt][nt][3] + bb1, 0.0f));
            }
        }
    } else {
        // ==================== QUARTER PATH: 32 x 64, warp tile 16x16 ====================
        const int wm2 = wid & 1, wn4 = wid >> 1;
        const int rowQ = m0 + wm2 * 16 + gid;      // and rowQ+8

        const uint32_t aAddr = xs_b +
            (uint32_t)(((wm2 * 16 + l7 + ((lane >> 3) & 1) * 8) * XS_STRIDE + ((lane >> 4) & 1) * 8) * 2);
        const uint32_t bAddr = bs_b +
            (uint32_t)(((wn4 * 16 + l7 + ((lane >> 4) & 1) * 8) * BS_STRIDE + ((lane >> 3) & 1) * 8) * 2);

        float acc[2][4];
        #pragma unroll
        for (int nt = 0; nt < 2; nt++)
            #pragma unroll
            for (int q = 0; q < 4; q++) acc[nt][q] = 0.0f;

        #pragma unroll 1
        for (int it = 0; it < NCHUNK; it++) {
            float xi0 = 128.0f * __ldg(x + (size_t)rowQ * DIM + it);
            float xi1 = 128.0f * __ldg(x + (size_t)(rowQ + 8) * DIM + it);

            CP_WAIT(1);
            __syncthreads();
            if (it + 2 < NCHUNK) G1_PREFETCH_B(it + 2);
            CP_COMMIT();

            const uint32_t bStage = bAddr + (uint32_t)(it % NSTAGE) * BS_STAGE_BYTES;
            float p[2][4];
            #pragma unroll
            for (int nt = 0; nt < 2; nt++)
                #pragma unroll
                for (int q = 0; q < 4; q++) p[nt][q] = 0.0f;

            const int s0 = it >> 4;
            for (int s = s0; s < 8; s++) {
                uint32_t a0[4], bA[4];
                LDSM4(a0, aAddr + (uint32_t)(s * 32));
                LDSM4(bA, bStage + (uint32_t)(s * 32));
                MMA_F16(p[0], a0, bA[0], bA[1]);
                MMA_F16(p[1], a0, bA[2], bA[3]);
            }
            #pragma unroll
            for (int nt = 0; nt < 2; nt++) {
                acc[nt][0] = fmaf(xi0, p[nt][0], acc[nt][0]);
                acc[nt][1] = fmaf(xi0, p[nt][1], acc[nt][1]);
                acc[nt][2] = fmaf(xi1, p[nt][2], acc[nt][2]);
                acc[nt][3] = fmaf(xi1, p[nt][3], acc[nt][3]);
            }
        }

        #pragma unroll
        for (int nt = 0; nt < 2; nt++) {
            int col = n0 + wn4 * 16 + nt * 8 + tg * 2;
            float bb0 = bias1[col], bb1 = bias1[col + 1];
            *(__half2*)(g_h + (size_t)rowQ * HID + col) =
                __floats2half2_rn(fmaxf(acc[nt][0] + bb0, 0.0f),
                                  fmaxf(acc[nt][1] + bb1, 0.0f));
            *(__half2*)(g_h + (size_t)(rowQ + 8) * HID + col) =
                __floats2half2_rn(fmaxf(acc[nt][2] + bb0, 0.0f),
                                  fmaxf(acc[nt][3] + bb1, 0.0f));
        }
    }
}

// ----------------------------------------------------------------------------
// Kernel 3: out = h @ W2 + b2  via fp16 mma.  CTA 128M x 64N, all K staged.
// ----------------------------------------------------------------------------
__global__ __launch_bounds__(256, 1) void k_layer2(const float* __restrict__ b2,
                                                   float* __restrict__ out) {
    extern __shared__ char smem_raw[];
    __half* ash = (__half*)smem_raw;                 // [128][L2_STRIDE]
    __half* bsh = ash + 128 * L2_STRIDE;             // [64][L2_STRIDE]
    const uint32_t as_b = smem_u32(ash);
    const uint32_t bs_b = smem_u32(bsh);

    const int tid  = threadIdx.x;
    const int lane = tid & 31;
    const int wid  = tid >> 5;
    const int wm   = wid & 3, wn = wid >> 2;
    const int gid  = lane >> 2, tg = lane & 3, l7 = lane & 7;
    const int m0 = (blockIdx.x & 31) * 128;
    const int n0 = (blockIdx.x >> 5) * 64;

    const __half* hg = g_h;
    const __half* w2g = g_w2t;

    // load A (h tile): 128 rows x 512 halfs
    #pragma unroll
    for (int r = 0; r < 32; r++) {
        int id = tid + r * 256;
        int row = id >> 6, chunk = id & 63;
        cp_async16(as_b + (uint32_t)(row * (L2_STRIDE * 2) + chunk * 16),
                   hg + (size_t)(m0 + row) * HID + chunk * 8);
    }
    // load B (W2^T tile): 64 rows x 512 halfs
    #pragma unroll
    for (int r = 0; r < 16; r++) {
        int id = tid + r * 256;
        int row = id >> 6, chunk = id & 63;
        cp_async16(bs_b + (uint32_t)(row * (L2_STRIDE * 2) + chunk * 16),
                   w2g + (size_t)(n0 + row) * HID + chunk * 8);
    }
    CP_COMMIT();
    CP_WAIT(0);
    __syncthreads();

    const uint32_t aAddr = as_b +
        (uint32_t)(((wm * 32 + l7 + ((lane >> 3) & 1) * 8) * L2_STRIDE + ((lane >> 4) & 1) * 8) * 2);
    const uint32_t bAddr = bs_b +
        (uint32_t)(((wn * 32 + l7 + ((lane >> 4) & 1) * 8) * L2_STRIDE + ((lane >> 3) & 1) * 8) * 2);

    float acc[2][4][4];
    #pragma unroll
    for (int mt = 0; mt < 2; mt++)
        #pragma unroll
        for (int nt = 0; nt < 4; nt++)
            #pragma unroll
            for (int q = 0; q < 4; q++) acc[mt][nt][q] = 0.0f;

    #pragma unroll 4
    for (int s = 0; s < 32; s++) {       // 32 k16-steps covering K=512
        uint32_t a0[4], a1[4], bA[4], bB[4];
        LDSM4(a0, aAddr + (uint32_t)(s * 32));
        LDSM4(a1, aAddr + (uint32_t)(16 * L2_STRIDE * 2 + s * 32));
        LDSM4(bA, bAddr + (uint32_t)(s * 32));
        LDSM4(bB, bAddr + (uint32_t)(16 * L2_STRIDE * 2 + s * 32));
        MMA_F16(acc[0][0], a0, bA[0], bA[1]);
        MMA_F16(acc[1][0], a1, bA[0], bA[1]);
        MMA_F16(acc[0][1], a0, bA[2], bA[3]);
        MMA_F16(acc[1][1], a1, bA[2], bA[3]);
        MMA_F16(acc[0][2], a0, bB[0], bB[1]);
        MMA_F16(acc[1][2], a1, bB[0], bB[1]);
        MMA_F16(acc[0][3], a0, bB[2], bB[3]);
        MMA_F16(acc[1][3], a1, bB[2], bB[3]);
    }

    #pragma unroll
    for (int mt = 0; mt < 2; mt++) {
        #pragma unroll
        for (int nt = 0; nt < 4; nt++) {
            int col = n0 + wn * 32 + nt * 8 + tg * 2;
            float bb0 = b2[col], bb1 = b2[col + 1];
            int rowA = m0 + wm * 32 + mt * 16 + gid;
            *(float2*)(out + (size_t)rowA * OUTD + col) =
                make_float2(acc[mt][nt][0] + bb0, acc[mt][nt][1] + bb1);
            *(float2*)(out + (size_t)(rowA + 8) * OUTD + col) =
                make_float2(acc[mt][nt][2] + bb0, acc[mt][nt][3] + bb1);
        }
    }
}

// ----------------------------------------------------------------------------
// Launch
// ----------------------------------------------------------------------------
extern "C" void kernel_launch(void* const* d_in, const int* in_sizes, int n_in,
                              void* d_out, int out_size) {
    const float *x = nullptr, *W1 = nullptr, *b1 = nullptr, *W2 = nullptr, *b2 = nullptr;
    for (int i = 0; i < n_in; i++) {
        switch (in_sizes[i]) {
            case BATCH * DIM:  x  = (const float*)d_in[i]; break;   // 524288
            case KTOT * HID:   W1 = (const float*)d_in[i]; break;   // 8388608
            case HID:          b1 = (const float*)d_in[i]; break;   // 512
            case HID * OUTD:   W2 = (const float*)d_in[i]; break;   // 131072
            case OUTD:         b2 = (const float*)d_in[i]; break;   // 256
            default: break;
        }
    }

    cudaFuncSetAttribute(k_gemm1,  cudaFuncAttributeMaxDynamicSharedMemorySize, G1_SMEM_BYTES);
    cudaFuncSetAttribute(k_layer2, cudaFuncAttributeMaxDynamicSharedMemorySize, L2_SMEM_BYTES);

    k_w1sym<<<dim3(DIM, HID / 32), dim3(32, 8)>>>(W1);
    k_w2t<<<dim3(HID / 64, OUTD / 32), dim3(32, 8)>>>(W2);
    k_gemm1<<<G1_GRID, 256, G1_SMEM_BYTES>>>(x, b1);
    k_layer2<<<128, 256, L2_SMEM_BYTES>>>(b2, (float*)d_out);
}

// round 13
// speedup vs baseline: 1.3086x; 1.3086x over previous
#include <cuda_runtime.h>
#include <cuda_fp16.h>
#include <cstdint>

// ----------------------------------------------------------------------------
// Problem constants
// ----------------------------------------------------------------------------
#define DIM 128            // input dim d
#define BATCH 4096
#define HID 512            // 2*OUTPUT_DIM
#define OUTD 256
#define KTOT (DIM * DIM)   // 16384
#define NITER 64           // 64 double-chunks; each = two i-blocks (256 k)

// GEMM1 tiling: CTA 128(M) x 64(N), 8 warps (warp tile 32x32), 256 CTAs, occ 2
#define XS_STRIDE 136      // fp16 x-tile row stride (halfs)  -> conflict-free ldmatrix
#define BS_STRIDE 264      // fp16 B-stage row stride (halfs): 2 i-blocks of 128 + pad
#define XS_HALFS (128 * XS_STRIDE)              // 17408 halfs = 34816 B
#define BS_STAGE_BYTES (64 * BS_STRIDE * 2)     // 33792 B
#define G1_SMEM_BYTES (XS_HALFS * 2 + 2 * BS_STAGE_BYTES)   // 102400 B

// Layer2: stage all of K=512 in smem
#define L2_STRIDE 520
#define L2_A_BYTES (128 * L2_STRIDE * 2)
#define L2_B_BYTES (64 * L2_STRIDE * 2)
#define L2_SMEM_BYTES (L2_A_BYTES + L2_B_BYTES) // 199680

// ----------------------------------------------------------------------------
// Device scratch (static allocation: allowed)
// ----------------------------------------------------------------------------
// W1sym^T fp16, [n][k], k=(i,j): j>i: W1[ij]+W1[ji]; j==i: W1[ii]; j<i: 0
__device__ __half g_w1t[HID * KTOT];     // 16.8MB
__device__ __half g_h[BATCH * HID];      // hidden activations, fp16 (4MB)
__device__ __half g_w2t[OUTD * HID];     // W2^T fp16 [n][k] (256KB)

// ----------------------------------------------------------------------------
// Helpers
// ----------------------------------------------------------------------------
__device__ __forceinline__ uint32_t smem_u32(const void* p) {
    uint32_t a;
    asm("{ .reg .u64 t; cvta.to.shared.u64 t, %1; cvt.u32.u64 %0, t; }" : "=r"(a) : "l"(p));
    return a;
}
__device__ __forceinline__ void cp_async16(uint32_t smem_addr, const void* gptr) {
    asm volatile("cp.async.cg.shared.global [%0], [%1], 16;" :: "r"(smem_addr), "l"(gptr) : "memory");
}
#define CP_COMMIT() asm volatile("cp.async.commit_group;" ::: "memory")
#define CP_WAIT(n)  asm volatile("cp.async.wait_group %0;" :: "n"(n) : "memory")

#define LDSM4(r, addr) \
    asm volatile("ldmatrix.sync.aligned.m8n8.x4.shared.b16 {%0,%1,%2,%3}, [%4];" \
        : "=r"((r)[0]), "=r"((r)[1]), "=r"((r)[2]), "=r"((r)[3]) : "r"(addr))

#define MMA_F16(d, a, bb0, bb1) \
    asm volatile("mma.sync.aligned.m16n8k16.row.col.f32.f16.f16.f32 " \
        "{%0,%1,%2,%3}, {%4,%5,%6,%7}, {%8,%9}, {%0,%1,%2,%3};" \
        : "+f"((d)[0]), "+f"((d)[1]), "+f"((d)[2]), "+f"((d)[3]) \
        : "r"((a)[0]), "r"((a)[1]), "r"((a)[2]), "r"((a)[3]), "r"(bb0), "r"(bb1))

// ----------------------------------------------------------------------------
// Kernel 1: symmetrize + transpose + fp16-convert W1.
// ----------------------------------------------------------------------------
__global__ __launch_bounds__(256) void k_w1sym(const float* __restrict__ W1) {
    __shared__ float ssum[128][33];
    const int i  = blockIdx.x;           // 0..127
    const int nb = blockIdx.y * 32;
    const int tx = threadIdx.x, ty = threadIdx.y;
    #pragma unroll
    for (int r = 0; r < 16; r++) {
        int j = ty + r * 8;
        float v = 0.0f;
        if (j > i) {
            v = W1[(size_t)(i * DIM + j) * HID + nb + tx]
              + W1[(size_t)(j * DIM + i) * HID + nb + tx];
        } else if (j == i) {
            v = W1[(size_t)(i * DIM + i) * HID + nb + tx];
        }
        ssum[j][tx] = v;
    }
    __syncthreads();
    #pragma unroll
    for (int r = 0; r < 4; r++) {
        int n = ty + r * 8;
        int j4 = tx * 4;
        __half2 h0 = __floats2half2_rn(ssum[j4 + 0][n], ssum[j4 + 1][n]);
        __half2 h1 = __floats2half2_rn(ssum[j4 + 2][n], ssum[j4 + 3][n]);
        uint2 pk = make_uint2(*(uint32_t*)&h0, *(uint32_t*)&h1);
        *(uint2*)(g_w1t + (size_t)(nb + n) * KTOT + i * DIM + j4) = pk;
    }
}

// ----------------------------------------------------------------------------
// Kernel 1b: transpose + fp16-convert W2 [512][256] -> g_w2t [256][512]
// ----------------------------------------------------------------------------
__global__ __launch_bounds__(256) void k_w2t(const float* __restrict__ W2) {
    __shared__ float t[32][66];
    const int kb = blockIdx.x * 64;
    const int nb = blockIdx.y * 32;
    const int tx = threadIdx.x, ty = threadIdx.y;
    #pragma unroll
    for (int r = 0; r < 8; r++) {
        int k = ty + r * 8;
        t[tx][k] = W2[(size_t)(kb + k) * OUTD + nb + tx];
    }
    __syncthreads();
    #pragma unroll
    for (int r = 0; r < 4; r++) {
        int n = ty + r * 8;
        __half2 h = __floats2half2_rn(t[n][tx * 2], t[n][tx * 2 + 1]);
        *(__half2*)(g_w2t + (size_t)(nb + n) * HID + kb + tx * 2) = h;
    }
}

// ----------------------------------------------------------------------------
// Kernel 2: H = relu( (d * x (x) x) @ W1 + b1 )  — symmetric triangle.
//   Two i-blocks per pipeline stage, 2-stage double buffer, 1 barrier/iter.
// ----------------------------------------------------------------------------
// Prefetch double-chunk it_ (i-blocks 2it_, 2it_+1) into buffer it_&1.
// Triangle: within block c, skip 16B segs with s < 2*(c>>4)  (j < 16*floor(c/16)).
#define G1_PREFETCH2(it_) do {                                                     \
    const int c0__ = 2 * (it_);                                                    \
    const int smin0__ = (c0__ >> 4) * 2;                                           \
    const int smin1__ = ((c0__ + 1) >> 4) * 2;                                     \
    const uint32_t buf__ = (uint32_t)((it_) & 1) * BS_STAGE_BYTES;                 \
    _Pragma("unroll")                                                              \
    for (int r__ = 0; r__ < 8; r__++) {                                            \
        int id__ = tid + r__ * 256;                                                \
        int row__ = id__ >> 5;            /* 0..63  (n within tile) */             \
        int seg__ = id__ & 31;            /* 0..31  (16B pieces of 512B) */        \
        int blk__ = seg__ >> 4;           /* 0/1 : which i-block */                \
        int s__   = seg__ & 15;                                                    \
        int smin__ = blk__ ? smin1__ : smin0__;                                    \
        if (s__ >= smin__)                                                         \
            cp_async16(bs_b + buf__ + (uint32_t)(row__ * (BS_STRIDE * 2) + blk__ * 256 + s__ * 16), \
                       w1g + (size_t)(n0 + row__) * KTOT + (c0__ + blk__) * 128 + s__ * 8); \
    }                                                                              \
} while (0)

__global__ __launch_bounds__(256, 2) void k_gemm1(const float* __restrict__ x,
                                                  const float* __restrict__ bias1) {
    extern __shared__ char smem_raw[];
    __half* xsh = (__half*)smem_raw;                 // [128][XS_STRIDE]
    __half* bsm = xsh + XS_HALFS;                    // 2 x [64][BS_STRIDE]
    const uint32_t xs_b = smem_u32(xsh);
    const uint32_t bs_b = smem_u32(bsm);

    const int tid  = threadIdx.x;
    const int lane = tid & 31;
    const int wid  = tid >> 5;
    const int wm   = wid & 3, wn = wid >> 2;
    const int gid  = lane >> 2;
    const int tg   = lane & 3;
    const int l7   = lane & 7;
    const int m0 = (blockIdx.x & 31) * 128;
    const int n0 = (blockIdx.x >> 5) * 64;

    const __half* w1g = g_w1t;

    // ---- prefetch stage 0 before x staging (overlap) ----
    G1_PREFETCH2(0);
    CP_COMMIT();

    // ---- stage x tile as fp16 [m][j] ----
    #pragma unroll
    for (int r = 0; r < 16; r++) {
        int id = tid + r * 256;
        int m = id >> 5, c4 = id & 31;
        float4 v = *(const float4*)(x + (size_t)(m0 + m) * DIM + c4 * 4);
        __half2 h0 = __floats2half2_rn(v.x, v.y);
        __half2 h1 = __floats2half2_rn(v.z, v.w);
        uint2 pk = make_uint2(*(uint32_t*)&h0, *(uint32_t*)&h1);
        *(uint2*)(xsh + m * XS_STRIDE + c4 * 4) = pk;
    }

    int rowt[4];
    rowt[0] = m0 + wm * 32 + gid;
    rowt[1] = rowt[0] + 8;
    rowt[2] = rowt[0] + 16;
    rowt[3] = rowt[0] + 24;

    const uint32_t aAddr = xs_b +
        (uint32_t)(((wm * 32 + l7 + ((lane >> 3) & 1) * 8) * XS_STRIDE + ((lane >> 4) & 1) * 8) * 2);
    const uint32_t bAddr = bs_b +
        (uint32_t)(((wn * 32 + l7 + ((lane >> 4) & 1) * 8) * BS_STRIDE + ((lane >> 3) & 1) * 8) * 2);

    float acc[2][4][4];
    #pragma unroll
    for (int mt = 0; mt < 2; mt++)
        #pragma unroll
        for (int nt = 0; nt < 4; nt++)
            #pragma unroll
            for (int q = 0; q < 4; q++) acc[mt][nt][q] = 0.0f;

    #pragma unroll 1
    for (int it = 0; it < NITER; it++) {
        CP_WAIT(0);              // double-chunk `it` landed
        __syncthreads();         // all warps done with buffer (it-1)&1 = (it+1)&1

        if (it + 1 < NITER) { G1_PREFETCH2(it + 1); CP_COMMIT(); }

        const uint32_t bStage = bAddr + (uint32_t)(it & 1) * BS_STAGE_BYTES;

        #pragma unroll
        for (int blk = 0; blk < 2; blk++) {
            const int c = 2 * it + blk;          // i index 0..127
            float xi[4];
            #pragma unroll
            for (int t = 0; t < 4; t++)
                xi[t] = 128.0f * __ldg(x + (size_t)rowt[t] * DIM + c);

            float p[2][4][4];
            #pragma unroll
            for (int mt = 0; mt < 2; mt++)
                #pragma unroll
                for (int nt = 0; nt < 4; nt++)
                    #pragma unroll
                    for (int q = 0; q < 4; q++) p[mt][nt][q] = 0.0f;

            const uint32_t bBlk = bStage + (uint32_t)(blk * 256);
            const int s0 = c >> 4;               // triangle start
            for (int s = s0; s < 8; s++) {
                uint32_t a0[4], a1[4], bA[4], bB[4];
                LDSM4(a0, aAddr + (uint32_t)(s * 32));
                LDSM4(a1, aAddr + (uint32_t)(16 * XS_STRIDE * 2 + s * 32));
                LDSM4(bA, bBlk + (uint32_t)(s * 32));
                LDSM4(bB, bBlk + (uint32_t)(16 * BS_STRIDE * 2 + s * 32));
                MMA_F16(p[0][0], a0, bA[0], bA[1]);
                MMA_F16(p[1][0], a1, bA[0], bA[1]);
                MMA_F16(p[0][1], a0, bA[2], bA[3]);
                MMA_F16(p[1][1], a1, bA[2], bA[3]);
                MMA_F16(p[0][2], a0, bB[0], bB[1]);
                MMA_F16(p[1][2], a1, bB[0], bB[1]);
                MMA_F16(p[0][3], a0, bB[2], bB[3]);
                MMA_F16(p[1][3], a1, bB[2], bB[3]);
            }
            #pragma unroll
            for (int mt = 0; mt < 2; mt++)
                #pragma unroll
                for (int nt = 0; nt < 4; nt++) {
                    acc[mt][nt][0] = fmaf(xi[mt * 2],     p[mt][nt][0], acc[mt][nt][0]);
                    acc[mt][nt][1] = fmaf(xi[mt * 2],     p[mt][nt][1], acc[mt][nt][1]);
                    acc[mt][nt][2] = fmaf(xi[mt * 2 + 1], p[mt][nt][2], acc[mt][nt][2]);
                    acc[mt][nt][3] = fmaf(xi[mt * 2 + 1], p[mt][nt][3], acc[mt][nt][3]);
                }
        }
    }

    // ---- Epilogue: +b1, relu, fp16 store ----
    #pragma unroll
    for (int mt = 0; mt < 2; mt++) {
        #pragma unroll
        for (int nt = 0; nt < 4; nt++) {
            int col = n0 + wn * 32 + nt * 8 + tg * 2;
            float bb0 = bias1[col], bb1 = bias1[col + 1];
            int rowA = m0 + wm * 32 + mt * 16 + gid;
            *(__half2*)(g_h + (size_t)rowA * HID + col) =
                __floats2half2_rn(fmaxf(acc[mt][nt][0] + bb0, 0.0f),
                                  fmaxf(acc[mt][nt][1] + bb1, 0.0f));
            *(__half2*)(g_h + (size_t)(rowA + 8) * HID + col) =
                __floats2half2_rn(fmaxf(acc[mt][nt][2] + bb0, 0.0f),
                                  fmaxf(acc[mt][nt][3] + bb1, 0.0f));
        }
    }
}

// ----------------------------------------------------------------------------
// Kernel 3: out = h @ W2 + b2  via fp16 mma.  CTA 128M x 64N, all K staged.
// ----------------------------------------------------------------------------
__global__ __launch_bounds__(256, 1) void k_layer2(const float* __restrict__ b2,
                                                   float* __restrict__ out) {
    extern __shared__ char smem_raw[];
    __half* ash = (__half*)smem_raw;                 // [128][L2_STRIDE]
    __half* bsh = ash + 128 * L2_STRIDE;             // [64][L2_STRIDE]
    const uint32_t as_b = smem_u32(ash);
    const uint32_t bs_b = smem_u32(bsh);

    const int tid  = threadIdx.x;
    const int lane = tid & 31;
    const int wid  = tid >> 5;
    const int wm   = wid & 3, wn = wid >> 2;
    const int gid  = lane >> 2, tg = lane & 3, l7 = lane & 7;
    const int m0 = (blockIdx.x & 31) * 128;
    const int n0 = (blockIdx.x >> 5) * 64;

    const __half* hg = g_h;
    const __half* w2g = g_w2t;

    #pragma unroll
    for (int r = 0; r < 32; r++) {
        int id = tid + r * 256;
        int row = id >> 6, chunk = id & 63;
        cp_async16(as_b + (uint32_t)(row * (L2_STRIDE * 2) + chunk * 16),
                   hg + (size_t)(m0 + row) * HID + chunk * 8);
    }
    #pragma unroll
    for (int r = 0; r < 16; r++) {
        int id = tid + r * 256;
        int row = id >> 6, chunk = id & 63;
        cp_async16(bs_b + (uint32_t)(row * (L2_STRIDE * 2) + chunk * 16),
                   w2g + (size_t)(n0 + row) * HID + chunk * 8);
    }
    CP_COMMIT();
    CP_WAIT(0);
    __syncthreads();

    const uint32_t aAddr = as_b +
        (uint32_t)(((wm * 32 + l7 + ((lane >> 3) & 1) * 8) * L2_STRIDE + ((lane >> 4) & 1) * 8) * 2);
    const uint32_t bAddr = bs_b +
        (uint32_t)(((wn * 32 + l7 + ((lane >> 4) & 1) * 8) * L2_STRIDE + ((lane >> 3) & 1) * 8) * 2);

    float acc[2][4][4];
    #pragma unroll
    for (int mt = 0; mt < 2; mt++)
        #pragma unroll
        for (int nt = 0; nt < 4; nt++)
            #pragma unroll
            for (int q = 0; q < 4; q++) acc[mt][nt][q] = 0.0f;

    #pragma unroll 4
    for (int s = 0; s < 32; s++) {
        uint32_t a0[4], a1[4], bA[4], bB[4];
        LDSM4(a0, aAddr + (uint32_t)(s * 32));
        LDSM4(a1, aAddr + (uint32_t)(16 * L2_STRIDE * 2 + s * 32));
        LDSM4(bA, bAddr + (uint32_t)(s * 32));
        LDSM4(bB, bAddr + (uint32_t)(16 * L2_STRIDE * 2 + s * 32));
        MMA_F16(acc[0][0], a0, bA[0], bA[1]);
        MMA_F16(acc[1][0], a1, bA[0], bA[1]);
        MMA_F16(acc[0][1], a0, bA[2], bA[3]);
        MMA_F16(acc[1][1], a1, bA[2], bA[3]);
        MMA_F16(acc[0][2], a0, bB[0], bB[1]);
        MMA_F16(acc[1][2], a1, bB[0], bB[1]);
        MMA_F16(acc[0][3], a0, bB[2], bB[3]);
        MMA_F16(acc[1][3], a1, bB[2], bB[3]);
    }

    #pragma unroll
    for (int mt = 0; mt < 2; mt++) {
        #pragma unroll
        for (int nt = 0; nt < 4; nt++) {
            int col = n0 + wn * 32 + nt * 8 + tg * 2;
            float bb0 = b2[col], bb1 = b2[col + 1];
            int rowA = m0 + wm * 32 + mt * 16 + gid;
            *(float2*)(out + (size_t)rowA * OUTD + col) =
                make_float2(acc[mt][nt][0] + bb0, acc[mt][nt][1] + bb1);
            *(float2*)(out + (size_t)(rowA + 8) * OUTD + col) =
                make_float2(acc[mt][nt][2] + bb0, acc[mt][nt][3] + bb1);
        }
    }
}

// ----------------------------------------------------------------------------
// Launch
// ----------------------------------------------------------------------------
extern "C" void kernel_launch(void* const* d_in, const int* in_sizes, int n_in,
                              void* d_out, int out_size) {
    const float *x = nullptr, *W1 = nullptr, *b1 = nullptr, *W2 = nullptr, *b2 = nullptr;
    for (int i = 0; i < n_in; i++) {
        switch (in_sizes[i]) {
            case BATCH * DIM:  x  = (const float*)d_in[i]; break;   // 524288
            case KTOT * HID:   W1 = (const float*)d_in[i]; break;   // 8388608
            case HID:          b1 = (const float*)d_in[i]; break;   // 512
            case HID * OUTD:   W2 = (const float*)d_in[i]; break;   // 131072
            case OUTD:         b2 = (const float*)d_in[i]; break;   // 256
            default: break;
        }
    }

    cudaFuncSetAttribute(k_gemm1,  cudaFuncAttributeMaxDynamicSharedMemorySize, G1_SMEM_BYTES);
    cudaFuncSetAttribute(k_layer2, cudaFuncAttributeMaxDynamicSharedMemorySize, L2_SMEM_BYTES);

    k_w1sym<<<dim3(DIM, HID / 32), dim3(32, 8)>>>(W1);
    k_w2t<<<dim3(HID / 64, OUTD / 32), dim3(32, 8)>>>(W2);
    k_gemm1<<<256, 256, G1_SMEM_BYTES>>>(x, b1);
    k_layer2<<<128, 256, L2_SMEM_BYTES>>>(b2, (float*)d_out);
}